// round 14
// baseline (speedup 1.0000x reference)
#include <cuda_runtime.h>
#include <cuda_fp16.h>

// LocalPosEnc2D: bilinear grid sample (513x513 x 24ch, fp32) + sinusoidal PE gating.
//   coords: (B,2) fp32   grids: (513*513, 24) fp32   out: (B,24) fp32
// Warp-aligned cooperative layout, 2 points per thread; the 8 gathers are
// issued via asm volatile ld.global.nc.v4 so ptxas CANNOT re-serialize them
// (R10/R11/R13 all collapsed to ~32-39 regs = serialized loads). Trig runs
// in the shadow of the in-flight loads.

#define GRID_ELEMS (513 * 513 * 24)
#define TWO_PI_F 6.28318530717958647692f
#define PI_F     3.14159265358979323846f

#define LDG_V4(dst, ptr)                                                    \
    asm volatile("ld.global.nc.v4.f32 {%0,%1,%2,%3}, [%4];"                 \
                 : "=f"(dst.x), "=f"(dst.y), "=f"(dst.z), "=f"(dst.w)       \
                 : "l"(ptr))

__device__ __forceinline__ void setup_point(
    const float2& c, float& lu, float& lv, int& idx00)
{
    float u = fminf(fmaxf(c.x, 0.0f), 1.0f - 1e-6f);
    float v = fminf(fmaxf(c.y, 0.0f), 1.0f - 1e-6f);
    float fu = u * 512.0f;
    float fv = v * 512.0f;
    int iu = (int)fu; iu = iu > 511 ? 511 : iu;
    int iv = (int)fv; iv = iv > 511 ? 511 : iv;
    lu = fu - (float)iu;
    lv = fv - (float)iv;
    idx00 = iu + iv * 513;
}

__device__ __forceinline__ void pe_gates(
    float lu, float lv, int j,
    float& pe0, float& pe1, float& pe2, float& pe3)
{
    // j=0,1 base (gate 1); j=2: cos(2^k*2pi*lu) j=3: sin(..lu)
    // j=4: cos(..lv) j=5: sin(..lv)
    float l = (j < 4) ? lu : lv;
    float ang = fmaf(l, TWO_PI_F, -PI_F);        // [-pi, pi)
    float s0 = -__sinf(ang);
    float c0 = -__cosf(ang);
    float s1 = 2.0f * s0 * c0;
    float c1 = fmaf(2.0f * c0, c0, -1.0f);
    float s2 = 2.0f * s1 * c1;
    float c2 = fmaf(2.0f * c1, c1, -1.0f);
    float s3 = 2.0f * s2 * c2;
    float c3 = fmaf(2.0f * c2, c2, -1.0f);

    bool use_sin = (j & 1);
    pe0 = use_sin ? s0 : c0;
    pe1 = use_sin ? s1 : c1;
    pe2 = use_sin ? s2 : c2;
    pe3 = use_sin ? s3 : c3;
    if (j < 2) { pe0 = 1.0f; pe1 = 1.0f; pe2 = 1.0f; pe3 = 1.0f; }
}

__device__ __forceinline__ void bilerp_store(
    float lu, float lv,
    const float4& a, const float4& bq, const float4& cq, const float4& dq,
    float pe0, float pe1, float pe2, float pe3,
    float4* outp)
{
    float wu0 = 1.0f - lu, wv0 = 1.0f - lv;
    float4 o;
    float t, b;
    t = a.x * wu0 + bq.x * lu;  b = cq.x * wu0 + dq.x * lu;
    o.x = __half2float(__float2half_rn((t * wv0 + b * lv) * pe0));
    t = a.y * wu0 + bq.y * lu;  b = cq.y * wu0 + dq.y * lu;
    o.y = __half2float(__float2half_rn((t * wv0 + b * lv) * pe1));
    t = a.z * wu0 + bq.z * lu;  b = cq.z * wu0 + dq.z * lu;
    o.z = __half2float(__float2half_rn((t * wv0 + b * lv) * pe2));
    t = a.w * wu0 + bq.w * lu;  b = cq.w * wu0 + dq.w * lu;
    o.w = __half2float(__float2half_rn((t * wv0 + b * lv) * pe3));
    __stcs(outp, o);
}

__global__ __launch_bounds__(256, 2) void lpe2d_kernel(
    const float2* __restrict__ coords,
    const float4* __restrict__ grids,   // grid row = 6 float4 (24 floats)
    float4*       __restrict__ out,     // out row  = 6 float4 (24 floats)
    int B)
{
    int gwarp = (blockIdx.x * blockDim.x + threadIdx.x) >> 5;
    int lane  = threadIdx.x & 31;
    if (lane >= 30) return;             // 2 idle lanes per warp (no straddle)
    int q = lane / 6;                   // local point 0..4
    int j = lane - q * 6;               // chunk role 0..5

    int p0 = gwarp * 10 + q;
    int p1 = p0 + 5;
    if (p0 >= B) return;
    bool has1 = (p1 < B);

    float2 c0 = coords[p0];
    float2 c1 = coords[has1 ? p1 : p0];

    float lu0, lv0, lu1, lv1;
    int i0, i1;
    setup_point(c0, lu0, lv0, i0);
    setup_point(c1, lu1, lv1, i1);

    const float4* r00 = grids + (size_t)i0 * 6;          // p0 rows iv   (192B)
    const float4* r01 = grids + (size_t)(i0 + 513) * 6;  // p0 rows iv+1
    const float4* r10 = grids + (size_t)i1 * 6;
    const float4* r11 = grids + (size_t)(i1 + 513) * 6;

    // Force all 8 gathers in flight simultaneously (volatile -> no sinking).
    float4 a0, b0, g0, d0, a1, b1, g1, d1;
    LDG_V4(a0, r00 + j);
    LDG_V4(b0, r00 + j + 6);
    LDG_V4(g0, r01 + j);
    LDG_V4(d0, r01 + j + 6);
    LDG_V4(a1, r10 + j);
    LDG_V4(b1, r10 + j + 6);
    LDG_V4(g1, r11 + j);
    LDG_V4(d1, r11 + j + 6);

    // Trig for BOTH points in the shadow of the in-flight loads.
    float pe00, pe01, pe02, pe03, pe10, pe11, pe12, pe13;
    pe_gates(lu0, lv0, j, pe00, pe01, pe02, pe03);
    pe_gates(lu1, lv1, j, pe10, pe11, pe12, pe13);

    bilerp_store(lu0, lv0, a0, b0, g0, d0, pe00, pe01, pe02, pe03,
                 out + (size_t)p0 * 6 + j);
    if (has1)
        bilerp_store(lu1, lv1, a1, b1, g1, d1, pe10, pe11, pe12, pe13,
                     out + (size_t)p1 * 6 + j);
}

extern "C" void kernel_launch(void* const* d_in, const int* in_sizes, int n_in,
                              void* d_out, int out_size) {
    // Bind inputs by size: grids has exactly 513*513*24 elements.
    int gi = -1, ci = -1;
    for (int i = 0; i < n_in; i++)
        if (in_sizes[i] == GRID_ELEMS && gi < 0) gi = i;
    for (int i = 0; i < n_in; i++)
        if (i != gi && ci < 0) ci = i;
    if (gi < 0) { gi = 1; ci = 0; }

    const float2* coords = (const float2*)d_in[ci];
    const float4* grids  = (const float4*)d_in[gi];
    float4*       out    = (float4*)d_out;
    int B = out_size / 24;                          // out is (B, 24) fp32
    long long warps = ((long long)B + 9) / 10;      // 10 points per warp
    long long threads_total = warps * 32;
    int threads = 256;
    int blocks = (int)((threads_total + threads - 1) / threads);
    lpe2d_kernel<<<blocks, threads>>>(coords, grids, out, B);
}

// round 15
// speedup vs baseline: 1.0288x; 1.0288x over previous
#include <cuda_runtime.h>
#include <cuda_fp16.h>

// LocalPosEnc2D: bilinear grid sample (513x513 x 24ch, fp32) + sinusoidal PE gating.
//   coords: (B,2) fp32   grids: (513*513, 24) fp32   out: (B,24) fp32
// Warp-aligned cooperative layout, 2 points per thread; the 8 gathers are
// issued via asm volatile ld.global.nc.v4 so ptxas cannot re-serialize them
// (regs=40 in R14 confirms they stay in flight). NO max-blocks cap: regs=40
// allows ~80% occupancy, giving occ x MLP ~ 320 outstanding loads/SM.

#define GRID_ELEMS (513 * 513 * 24)
#define TWO_PI_F 6.28318530717958647692f
#define PI_F     3.14159265358979323846f

#define LDG_V4(dst, ptr)                                                    \
    asm volatile("ld.global.nc.v4.f32 {%0,%1,%2,%3}, [%4];"                 \
                 : "=f"(dst.x), "=f"(dst.y), "=f"(dst.z), "=f"(dst.w)       \
                 : "l"(ptr))

__device__ __forceinline__ void setup_point(
    const float2& c, float& lu, float& lv, int& idx00)
{
    float u = fminf(fmaxf(c.x, 0.0f), 1.0f - 1e-6f);
    float v = fminf(fmaxf(c.y, 0.0f), 1.0f - 1e-6f);
    float fu = u * 512.0f;
    float fv = v * 512.0f;
    int iu = (int)fu; iu = iu > 511 ? 511 : iu;
    int iv = (int)fv; iv = iv > 511 ? 511 : iv;
    lu = fu - (float)iu;
    lv = fv - (float)iv;
    idx00 = iu + iv * 513;
}

__device__ __forceinline__ void pe_gates(
    float lu, float lv, int j,
    float& pe0, float& pe1, float& pe2, float& pe3)
{
    // j=0,1 base (gate 1); j=2: cos(2^k*2pi*lu) j=3: sin(..lu)
    // j=4: cos(..lv) j=5: sin(..lv)
    float l = (j < 4) ? lu : lv;
    float ang = fmaf(l, TWO_PI_F, -PI_F);        // [-pi, pi)
    float s0 = -__sinf(ang);
    float c0 = -__cosf(ang);
    float s1 = 2.0f * s0 * c0;
    float c1 = fmaf(2.0f * c0, c0, -1.0f);
    float s2 = 2.0f * s1 * c1;
    float c2 = fmaf(2.0f * c1, c1, -1.0f);
    float s3 = 2.0f * s2 * c2;
    float c3 = fmaf(2.0f * c2, c2, -1.0f);

    bool use_sin = (j & 1);
    pe0 = use_sin ? s0 : c0;
    pe1 = use_sin ? s1 : c1;
    pe2 = use_sin ? s2 : c2;
    pe3 = use_sin ? s3 : c3;
    if (j < 2) { pe0 = 1.0f; pe1 = 1.0f; pe2 = 1.0f; pe3 = 1.0f; }
}

__device__ __forceinline__ void bilerp_store(
    float lu, float lv,
    const float4& a, const float4& bq, const float4& cq, const float4& dq,
    float pe0, float pe1, float pe2, float pe3,
    float4* outp)
{
    float wu0 = 1.0f - lu, wv0 = 1.0f - lv;
    float4 o;
    float t, b;
    t = a.x * wu0 + bq.x * lu;  b = cq.x * wu0 + dq.x * lu;
    o.x = __half2float(__float2half_rn((t * wv0 + b * lv) * pe0));
    t = a.y * wu0 + bq.y * lu;  b = cq.y * wu0 + dq.y * lu;
    o.y = __half2float(__float2half_rn((t * wv0 + b * lv) * pe1));
    t = a.z * wu0 + bq.z * lu;  b = cq.z * wu0 + dq.z * lu;
    o.z = __half2float(__float2half_rn((t * wv0 + b * lv) * pe2));
    t = a.w * wu0 + bq.w * lu;  b = cq.w * wu0 + dq.w * lu;
    o.w = __half2float(__float2half_rn((t * wv0 + b * lv) * pe3));
    __stcs(outp, o);
}

__global__ __launch_bounds__(256) void lpe2d_kernel(
    const float2* __restrict__ coords,
    const float4* __restrict__ grids,   // grid row = 6 float4 (24 floats)
    float4*       __restrict__ out,     // out row  = 6 float4 (24 floats)
    int B)
{
    int gwarp = (blockIdx.x * blockDim.x + threadIdx.x) >> 5;
    int lane  = threadIdx.x & 31;
    if (lane >= 30) return;             // 2 idle lanes per warp (no straddle)
    int q = lane / 6;                   // local point 0..4
    int j = lane - q * 6;               // chunk role 0..5

    int p0 = gwarp * 10 + q;
    int p1 = p0 + 5;
    if (p0 >= B) return;
    bool has1 = (p1 < B);

    float2 c0 = coords[p0];
    float2 c1 = coords[has1 ? p1 : p0];

    float lu0, lv0, lu1, lv1;
    int i0, i1;
    setup_point(c0, lu0, lv0, i0);
    setup_point(c1, lu1, lv1, i1);

    const float4* r00 = grids + (size_t)i0 * 6;          // p0 rows iv   (192B)
    const float4* r01 = grids + (size_t)(i0 + 513) * 6;  // p0 rows iv+1
    const float4* r10 = grids + (size_t)i1 * 6;
    const float4* r11 = grids + (size_t)(i1 + 513) * 6;

    // Force all 8 gathers in flight simultaneously (volatile -> no sinking).
    float4 a0, b0, g0, d0, a1, b1, g1, d1;
    LDG_V4(a0, r00 + j);
    LDG_V4(b0, r00 + j + 6);
    LDG_V4(g0, r01 + j);
    LDG_V4(d0, r01 + j + 6);
    LDG_V4(a1, r10 + j);
    LDG_V4(b1, r10 + j + 6);
    LDG_V4(g1, r11 + j);
    LDG_V4(d1, r11 + j + 6);

    // Trig for BOTH points in the shadow of the in-flight loads.
    float pe00, pe01, pe02, pe03, pe10, pe11, pe12, pe13;
    pe_gates(lu0, lv0, j, pe00, pe01, pe02, pe03);
    pe_gates(lu1, lv1, j, pe10, pe11, pe12, pe13);

    bilerp_store(lu0, lv0, a0, b0, g0, d0, pe00, pe01, pe02, pe03,
                 out + (size_t)p0 * 6 + j);
    if (has1)
        bilerp_store(lu1, lv1, a1, b1, g1, d1, pe10, pe11, pe12, pe13,
                     out + (size_t)p1 * 6 + j);
}

extern "C" void kernel_launch(void* const* d_in, const int* in_sizes, int n_in,
                              void* d_out, int out_size) {
    // Bind inputs by size: grids has exactly 513*513*24 elements.
    int gi = -1, ci = -1;
    for (int i = 0; i < n_in; i++)
        if (in_sizes[i] == GRID_ELEMS && gi < 0) gi = i;
    for (int i = 0; i < n_in; i++)
        if (i != gi && ci < 0) ci = i;
    if (gi < 0) { gi = 1; ci = 0; }

    const float2* coords = (const float2*)d_in[ci];
    const float4* grids  = (const float4*)d_in[gi];
    float4*       out    = (float4*)d_out;
    int B = out_size / 24;                          // out is (B, 24) fp32
    long long warps = ((long long)B + 9) / 10;      // 10 points per warp
    long long threads_total = warps * 32;
    int threads = 256;
    int blocks = (int)((threads_total + threads - 1) / threads);
    lpe2d_kernel<<<blocks, threads>>>(coords, grids, out, B);
}